// round 11
// baseline (speedup 1.0000x reference)
#include <cuda_runtime.h>
#include <cstdint>

#define N_DENSE    64
#define N_SAMPLES  121
#define N_CHANNELS 384
#define BATCH      2048
#define ROW_IN     (N_DENSE * (1 + N_SAMPLES))   // 7808 floats per input row
#define ROW_OUT    (N_CHANNELS * N_SAMPLES)      // 46464 floats per output batch
#define N_VEC      (ROW_OUT / 4)                 // 11616 float4 per batch row
#define DATA_F     (N_DENSE * N_SAMPLES)         // 7744 floats of sample data
#define NTHREADS   384                           // 12 warps -> 5 CTAs/SM

__device__ __forceinline__ void cp16(float* dst_smem, const float4* src) {
    uint32_t d = (uint32_t)__cvta_generic_to_shared(dst_smem);
    asm volatile("cp.async.cg.shared.global [%0], [%1], 16;\n" :: "r"(d), "l"(src));
}

// Two-pass gather: ~85% of channel chains are empty, so ~85% of output vec4s
// are zeros that depend ONLY on the 64-float index columns. Pass 1 stores
// those immediately while cp.async streams the 31KB data tile in the
// background; pass 2 (after the async copy lands) handles only the non-empty
// vec4s with the chain-walk body. Each vec4 is written exactly once.
__global__ __launch_bounds__(NTHREADS)
void sparse_input_gather_v11(const float* __restrict__ in,
                             float* __restrict__ out)
{
    __shared__ float sdata[DATA_F + 4];   // staged [64][121]
    __shared__ int   head[N_CHANNELS];    // chain head per channel (-1 = empty)
    __shared__ int   nxt[N_DENSE];        // next slot in chain

    const int b = blockIdx.x;
    const int t = threadIdx.x;

    const float* __restrict__ row  = in + (size_t)b * ROW_IN;
    const float* __restrict__ data = row + N_DENSE;

    // ---- phase 0: index load, head init, background data copy ----
    int my_c = 0;
    if (t < N_DENSE)
        my_c = (int)__ldg(&row[t]);       // in [0, N_CHANNELS) by construction
    if (t < N_CHANNELS) head[t] = -1;

    {
        const float4* __restrict__ src = reinterpret_cast<const float4*>(data);
        #pragma unroll
        for (int i = t; i < DATA_F / 4; i += NTHREADS)   // 1936 vec4, fire-and-forget
            cp16(&sdata[4 * i], &src[i]);
        asm volatile("cp.async.commit_group;\n" ::: "memory");
    }
    __syncthreads();                       // head[] init visible
    if (t < N_DENSE)
        nxt[t] = atomicExch(&head[my_c], t);
    __syncthreads();                       // chains visible (sdata NOT yet)

    float4* __restrict__ ovec = reinterpret_cast<float4*>(out + (size_t)b * ROW_OUT);
    const float4 zero4 = make_float4(0.f, 0.f, 0.f, 0.f);

    // ---- pass 1: store zeros for empty vec4s (no dependence on sdata) ----
    {
        int c = (4 * t) / N_SAMPLES;
        int s = 4 * t - c * N_SAMPLES;
        #pragma unroll 4
        for (int v = t; v < N_VEC; v += NTHREADS) {
            bool empty;
            if (s <= N_SAMPLES - 4)
                empty = (head[c] < 0);
            else
                empty = (head[c] < 0) && (head[c + 1] < 0);
            if (empty) __stcs(&ovec[v], zero4);

            s += 84; c += 12;                       // stride 1536 = 12*121 + 84
            if (s >= N_SAMPLES) { s -= N_SAMPLES; c++; }
        }
    }

    asm volatile("cp.async.wait_group 0;\n" ::: "memory");
    __syncthreads();                       // sdata visible

    // ---- pass 2: non-empty vec4s via chain walks ----
    {
        int c = (4 * t) / N_SAMPLES;
        int s = 4 * t - c * N_SAMPLES;
        #pragma unroll 2
        for (int v = t; v < N_VEC; v += NTHREADS) {
            if (s <= N_SAMPLES - 4) {
                int d = head[c];
                if (d >= 0) {                       // fast path, non-empty
                    float4 acc = zero4;
                    do {
                        const float* g = sdata + d * N_SAMPLES + s;
                        acc.x += g[0];
                        acc.y += g[1];
                        acc.z += g[2];
                        acc.w += g[3];
                        d = nxt[d];
                    } while (d >= 0);
                    __stcs(&ovec[v], acc);
                }
            } else {
                int d  = head[c];
                int d2 = head[c + 1];
                if (d >= 0 || d2 >= 0) {            // straddle, non-empty
                    const int nA = N_SAMPLES - s;   // in {1,2,3}
                    float4 acc = zero4;
                    while (d >= 0) {                // walk A: channel c
                        const float* g = sdata + d * N_SAMPLES + s;
                        acc.x += g[0];
                        if (nA > 1) acc.y += g[1];
                        if (nA > 2) acc.z += g[2];
                        d = nxt[d];
                    }
                    while (d2 >= 0) {               // walk B: channel c+1
                        const float* g2 = sdata + d2 * N_SAMPLES - nA;
                        if (nA < 2) acc.y += g2[1];
                        if (nA < 3) acc.z += g2[2];
                        acc.w += g2[3];
                        d2 = nxt[d2];
                    }
                    __stcs(&ovec[v], acc);
                }
            }
            s += 84; c += 12;
            if (s >= N_SAMPLES) { s -= N_SAMPLES; c++; }
        }
    }
}

extern "C" void kernel_launch(void* const* d_in, const int* in_sizes, int n_in,
                              void* d_out, int out_size)
{
    const float* in  = (const float*)d_in[0];
    float*       out = (float*)d_out;
    sparse_input_gather_v11<<<BATCH, NTHREADS>>>(in, out);
}

// round 12
// speedup vs baseline: 1.1485x; 1.1485x over previous
#include <cuda_runtime.h>
#include <cstdint>

#define N_DENSE    64
#define N_SAMPLES  121
#define N_CHANNELS 384
#define BATCH      2048
#define ROW_IN     (N_DENSE * (1 + N_SAMPLES))   // 7808 floats per input row
#define ROW_OUT    (N_CHANNELS * N_SAMPLES)      // 46464 floats per output batch
#define N_VEC      (ROW_OUT / 4)                 // 11616 float4 per batch row
#define DATA_F     (N_DENSE * N_SAMPLES)         // 7744 floats of sample data
#define NTHREADS   384                           // 12 warps -> 5 CTAs/SM

// FINAL kernel — best measured configuration (R10: 67.8us kernel, 71.6% DRAM,
// 5.67 TB/s writes-only = HBM streaming-write ceiling).
//
// One CTA per batch row:
//   phase 1: stage the 31KB data tile in smem (float4 copy), build a
//            per-channel inverted index (linked lists via shared atomicExch).
//   phase 2: flat vec4 output mapping with incremental (c,s) tracking —
//            full-warp contiguous STG.128 (wavefront-optimal stores);
//            chain walks read smem (29cyc LDS, ~85% of chains empty);
//            straddle vec4s via two predicated walks (channels c, c+1);
//            __stcs streaming stores keep the 64MB input L2-resident.
//
// A/B-tested and rejected: direct-L2 gather (-12%), persistent CTAs +
// cp.async double-buffer (-4%), two-pass zero/nonzero split (-13%, ragged
// store wavefronts), head-prefetch pipelining (0%), 320/512-thread shapes.
__global__ __launch_bounds__(NTHREADS)
void sparse_input_gather_final(const float* __restrict__ in,
                               float* __restrict__ out)
{
    __shared__ float sdata[DATA_F + 4];   // staged [64][121]
    __shared__ int   head[N_CHANNELS];    // chain head per channel (-1 = empty)
    __shared__ int   nxt[N_DENSE];        // next slot in chain

    const int b = blockIdx.x;
    const int t = threadIdx.x;

    const float* __restrict__ row  = in + (size_t)b * ROW_IN;
    const float* __restrict__ data = row + N_DENSE;

    // ---- phase 1: stage data + build inverted index ----
    int my_c = 0;
    if (t < N_DENSE)
        my_c = (int)__ldg(&row[t]);       // in [0, N_CHANNELS) by construction
    if (t < N_CHANNELS) head[t] = -1;

    {
        const float4* __restrict__ src = reinterpret_cast<const float4*>(data);
        float4* __restrict__ dst = reinterpret_cast<float4*>(sdata);
        #pragma unroll
        for (int i = t; i < DATA_F / 4; i += NTHREADS)   // 1936 vec4
            dst[i] = src[i];
    }
    __syncthreads();
    if (t < N_DENSE)
        nxt[t] = atomicExch(&head[my_c], t);
    __syncthreads();

    // ---- phase 2: gather ----
    float4* __restrict__ ovec = reinterpret_cast<float4*>(out + (size_t)b * ROW_OUT);

    // (c, s) for p = 4t; stride NTHREADS vec4 = 1536 floats = 12*121 + 84
    int c = (4 * t) / N_SAMPLES;
    int s = 4 * t - c * N_SAMPLES;

    #pragma unroll 4
    for (int v = t; v < N_VEC; v += NTHREADS) {
        float4 acc = make_float4(0.f, 0.f, 0.f, 0.f);

        if (s <= N_SAMPLES - 4) {
            // fast path: all 4 samples in channel c (~85% of chains empty)
            int d = head[c];
            while (d >= 0) {
                const float* g = sdata + d * N_SAMPLES + s;
                acc.x += g[0];
                acc.y += g[1];
                acc.z += g[2];
                acc.w += g[3];
                d = nxt[d];
            }
        } else {
            // straddle: nA = 121 - s in {1,2,3} samples from c, rest from c+1
            const int nA = N_SAMPLES - s;
            int d = head[c];
            while (d >= 0) {                           // walk A: channel c
                const float* g = sdata + d * N_SAMPLES + s;
                acc.x += g[0];
                if (nA > 1) acc.y += g[1];
                if (nA > 2) acc.z += g[2];
                d = nxt[d];
            }
            int d2 = head[c + 1];
            while (d2 >= 0) {                          // walk B: channel c+1
                const float* g2 = sdata + d2 * N_SAMPLES - nA;  // + j, j in [nA,3]
                if (nA < 2) acc.y += g2[1];
                if (nA < 3) acc.z += g2[2];
                acc.w += g2[3];
                d2 = nxt[d2];
            }
        }
        __stcs(&ovec[v], acc);          // streaming 128-bit store, full-warp coalesced

        // advance (c, s) by 1536 flat elements: c += 12, s += 84, wrap
        s += 84; c += 12;
        if (s >= N_SAMPLES) { s -= N_SAMPLES; c++; }
    }
}

extern "C" void kernel_launch(void* const* d_in, const int* in_sizes, int n_in,
                              void* d_out, int out_size)
{
    const float* in  = (const float*)d_in[0];
    float*       out = (float*)d_out;
    sparse_input_gather_final<<<BATCH, NTHREADS>>>(in, out);
}